// round 1
// baseline (speedup 1.0000x reference)
#include <cuda_runtime.h>
#include <cuda_bf16.h>
#include <math.h>

// Problem constants
#define BB 32          // batch
#define TT 32          // tgt length (steps = 31)
#define SS 64          // src length
#define HH 512         // hidden
#define EE 512         // emb dim
#define VV 32000       // vocab
#define T1 (TT-1)      // 31
#define TBV ((size_t)T1*BB*VV)   // 31,744,000
#define BH (BB*HH)     // 16384

// -------- persistent device scratch (static globals: allocation-free) --------
__device__ float g_h[BH];
__device__ float g_c[BH];
__device__ float g_proj[BB*SS*HH];           // [s][b][k] actually (s*B+b) rows
__device__ float g_XC[BB*2*HH];              // [b][h2(512) | ctx(512)]
__device__ float g_Gpart[6*BB*4*HH];         // split-K partials for gates
__device__ float g_A2part[8*BB*HH];          // split-K partials for ah2
__device__ float g_ah_all[T1*BH];            // ah2 per step  [t][b][h] == [992][512]
__device__ float g_zero[BH];                 // stays zero (never written)
__device__ int   g_argmax[T1*BB];
__device__ float g_logits[T1*BB*VV];         // fallback logits buffer (bss, 127MB)

__device__ __forceinline__ float sigf(float x){ return 1.0f/(1.0f+expf(-x)); }

// ---------------------------------------------------------------------------
// Generic tiled SGEMM:  C[M,N] = A[M,K] @ B[N,K]^T (+bias, +tanh)
// If gridDim.z > 1: split-K, write raw partials to Cpart[z][M][N] (no bias/act)
// Requires N % BN == 0, (K/gridDim.z) % BK == 0. M is guarded.
// ---------------------------------------------------------------------------
template<int BM,int BN,int BK,int TM,int TN,int ACT>
__global__ void sgemm(const float* __restrict__ A, const float* __restrict__ B,
                      const float* __restrict__ bias, float* __restrict__ C,
                      int M, int N, int K, float* __restrict__ Cpart)
{
    constexpr int THREADS = (BM/TM)*(BN/TN);
    static_assert(THREADS == 256, "256 threads expected");
    __shared__ float As[BK][BM+4];
    __shared__ float Bs[BK][BN+4];
    const int tid = threadIdx.x;
    const int bm = blockIdx.y*BM, bn = blockIdx.x*BN;
    const int KS = gridDim.z;
    const int kchunk = K / KS;
    const int kbeg = blockIdx.z * kchunk;
    const int tx = tid % (BN/TN);
    const int ty = tid / (BN/TN);
    float acc[TM][TN];
    #pragma unroll
    for (int i=0;i<TM;i++)
        #pragma unroll
        for (int j=0;j<TN;j++) acc[i][j]=0.f;

    for (int k0 = kbeg; k0 < kbeg + kchunk; k0 += BK) {
        #pragma unroll
        for (int i=0;i<(BM*BK)/THREADS;i++){
            int idx = tid + i*THREADS; int m = idx/BK, k = idx%BK;
            int gm = bm + m;
            As[k][m] = (gm < M) ? A[(size_t)gm*K + k0 + k] : 0.f;
        }
        #pragma unroll
        for (int i=0;i<(BN*BK)/THREADS;i++){
            int idx = tid + i*THREADS; int n = idx/BK, k = idx%BK;
            Bs[k][n] = B[(size_t)(bn+n)*K + k0 + k];
        }
        __syncthreads();
        #pragma unroll
        for (int kk=0;kk<BK;kk++){
            float a[TM], b[TN];
            #pragma unroll
            for (int i=0;i<TM;i++) a[i] = As[kk][ty*TM+i];
            #pragma unroll
            for (int j=0;j<TN;j++) b[j] = Bs[kk][tx*TN+j];
            #pragma unroll
            for (int i=0;i<TM;i++)
                #pragma unroll
                for (int j=0;j<TN;j++) acc[i][j] += a[i]*b[j];
        }
        __syncthreads();
    }

    if (KS == 1) {
        #pragma unroll
        for (int i=0;i<TM;i++){
            int gm = bm + ty*TM + i;
            if (gm >= M) continue;
            #pragma unroll
            for (int j=0;j<TN;j++){
                int gn = bn + tx*TN + j;
                float v = acc[i][j];
                if (bias) v += bias[gn];
                if (ACT == 1) v = tanhf(v);
                C[(size_t)gm*N + gn] = v;
            }
        }
    } else {
        #pragma unroll
        for (int i=0;i<TM;i++){
            int gm = bm + ty*TM + i;
            if (gm >= M) continue;
            #pragma unroll
            for (int j=0;j<TN;j++){
                int gn = bn + tx*TN + j;
                Cpart[(size_t)blockIdx.z*M*N + (size_t)gm*N + gn] = acc[i][j];
            }
        }
    }
}

// ---------------------------------------------------------------------------
// Gates GEMM (per step t), split-K=6 via gridDim.z.
// G[b,j] = sum_k X[b,k] * W[j,k]   (partials only; bias added in lstm kernel)
//   X[b,k] = emb[tgt[b,t]][k]          (k < 512)
//          = ah_prev[b][k-512]         (512 <= k < 1024)
//          = g_h[b][k-1024]            (1024 <= k < 1536)
//   W[j,k] = W_ih[j][k]  (k<1024)  |  W_hh[j][k-1024]
// BM=32, BN=64, BK=16, 256 threads, TM=2, TN=4. grid (32,1,6)
// ---------------------------------------------------------------------------
__global__ void k_gates(const int* __restrict__ tgt,
                        const float* __restrict__ emb,
                        const float* __restrict__ W_ih,
                        const float* __restrict__ W_hh,
                        const float* __restrict__ ahp,
                        int t)
{
    constexpr int BM=32, BN=64, BK=16, TM=2, TN=4, THREADS=256;
    __shared__ float As[BK][BM+4];
    __shared__ float Bs[BK][BN+4];
    __shared__ int   ws[BB];
    const int tid = threadIdx.x;
    const int bn = blockIdx.x * BN;
    const int kbeg = blockIdx.z * (1536/6);          // 256 per split
    const int tx = tid % (BN/TN);
    const int ty = tid / (BN/TN);
    if (tid < BB) ws[tid] = tgt[tid*TT + t];
    float acc[TM][TN];
    #pragma unroll
    for (int i=0;i<TM;i++)
        #pragma unroll
        for (int j=0;j<TN;j++) acc[i][j]=0.f;
    __syncthreads();

    for (int k0 = kbeg; k0 < kbeg + 256; k0 += BK) {
        #pragma unroll
        for (int i=0;i<(BM*BK)/THREADS;i++){
            int idx = tid + i*THREADS; int m = idx/BK, k = idx%BK;
            int kg = k0 + k;
            float v;
            if (kg < EE)            v = emb[(size_t)ws[m]*EE + kg];
            else if (kg < EE+HH)    v = ahp[m*HH + (kg-EE)];
            else                    v = g_h[m*HH + (kg-EE-HH)];
            As[k][m] = v;
        }
        #pragma unroll
        for (int i=0;i<(BN*BK)/THREADS;i++){
            int idx = tid + i*THREADS; int n = idx/BK, k = idx%BK;
            int j = bn + n; int kg = k0 + k;
            Bs[k][n] = (kg < EE+HH) ? W_ih[(size_t)j*(EE+HH) + kg]
                                    : W_hh[(size_t)j*HH + (kg-EE-HH)];
        }
        __syncthreads();
        #pragma unroll
        for (int kk=0;kk<BK;kk++){
            float a[TM], b[TN];
            #pragma unroll
            for (int i=0;i<TM;i++) a[i] = As[kk][ty*TM+i];
            #pragma unroll
            for (int j=0;j<TN;j++) b[j] = Bs[kk][tx*TN+j];
            #pragma unroll
            for (int i=0;i<TM;i++)
                #pragma unroll
                for (int j=0;j<TN;j++) acc[i][j] += a[i]*b[j];
        }
        __syncthreads();
    }
    #pragma unroll
    for (int i=0;i<TM;i++){
        int b = ty*TM + i;
        #pragma unroll
        for (int j=0;j<TN;j++){
            int n = bn + tx*TN + j;
            g_Gpart[(size_t)blockIdx.z*BB*4*HH + b*4*HH + n] = acc[i][j];
        }
    }
}

// LSTM cell: reduce gate partials + biases, update h,c; h2 -> g_XC[:,0:512]
__global__ void k_lstm(const float* __restrict__ b_ih, const float* __restrict__ b_hh)
{
    int idx = blockIdx.x*blockDim.x + threadIdx.x;
    if (idx >= BH) return;
    int b = idx >> 9, h = idx & 511;
    float gv[4];
    #pragma unroll
    for (int q=0;q<4;q++){
        int j = q*HH + h;
        float s = b_ih[j] + b_hh[j];
        #pragma unroll
        for (int z=0;z<6;z++) s += g_Gpart[(size_t)z*BB*4*HH + b*4*HH + j];
        gv[q] = s;
    }
    float ig = sigf(gv[0]);
    float fg = sigf(gv[1]);
    float gg = tanhf(gv[2]);
    float og = sigf(gv[3]);
    float c  = fg * g_c[idx] + ig * gg;
    g_c[idx] = c;
    float h2 = og * tanhf(c);
    g_h[idx] = h2;
    g_XC[b*2*HH + h] = h2;
}

// Attention: one block per batch row b. 512 threads.
__global__ void k_attn(const int* __restrict__ lens, const float* __restrict__ enc)
{
    __shared__ float hh[HH];
    __shared__ float sc[SS];
    const int b   = blockIdx.x;
    const int tid = threadIdx.x;
    const int len = lens[b];

    hh[tid] = g_h[b*HH + tid];
    __syncthreads();

    // scores: 16 warps, warp w handles s = w, w+16, w+32, w+48
    int w = tid >> 5, l = tid & 31;
    for (int s = w; s < SS; s += 16) {
        const float* pr = &g_proj[((size_t)s*BB + b)*HH];
        float sum = 0.f;
        for (int k = l; k < HH; k += 32) sum += hh[k] * pr[k];
        #pragma unroll
        for (int off=16; off>0; off>>=1) sum += __shfl_xor_sync(0xffffffffu, sum, off);
        if (l == 0) sc[s] = (s < len) ? sum : -1e9f;
    }
    __syncthreads();

    // softmax over 64 entries by warp 0
    if (tid < 32) {
        float v0 = sc[tid], v1 = sc[tid+32];
        float m = fmaxf(v0, v1);
        #pragma unroll
        for (int off=16; off>0; off>>=1) m = fmaxf(m, __shfl_xor_sync(0xffffffffu, m, off));
        float e0 = expf(v0 - m), e1 = expf(v1 - m);
        float s = e0 + e1;
        #pragma unroll
        for (int off=16; off>0; off>>=1) s += __shfl_xor_sync(0xffffffffu, s, off);
        float inv = 1.0f / s;
        sc[tid]    = e0 * inv;
        sc[tid+32] = e1 * inv;
    }
    __syncthreads();

    // ctx[b][h] = sum_s align[s] * enc[s][b][h]
    float acc = 0.f;
    #pragma unroll 4
    for (int s = 0; s < SS; s++)
        acc += sc[s] * enc[((size_t)s*BB + b)*HH + tid];
    g_XC[b*2*HH + HH + tid] = acc;
}

// ah2 finalize: reduce split-K partials + bias, tanh, store into g_ah_all[t]
__global__ void k_ah2fin(const float* __restrict__ b_c, int t)
{
    int idx = blockIdx.x*blockDim.x + threadIdx.x;
    if (idx >= BH) return;
    int n = idx & 511;
    float s = b_c[n];
    #pragma unroll
    for (int z=0;z<8;z++) s += g_A2part[(size_t)z*BH + idx];
    g_ah_all[(size_t)t*BH + idx] = tanhf(s);
}

__global__ void k_init(const float* __restrict__ h0, const float* __restrict__ c0)
{
    int idx = blockIdx.x*blockDim.x + threadIdx.x;
    if (idx >= BH) return;
    g_h[idx] = h0[idx];
    g_c[idx] = c0[idx];
}

// log-softmax (in place) + argmax per row. block per row, 256 threads.
__global__ void k_logsoftmax(float* __restrict__ logits)
{
    __shared__ float sf[256];
    __shared__ int   si[256];
    const int row = blockIdx.x;
    const int tid = threadIdx.x;
    float* x = logits + (size_t)row * VV;

    float m = -INFINITY; int mi = 0;
    for (int c = tid; c < VV; c += 256) {
        float v = x[c];
        if (v > m) { m = v; mi = c; }
    }
    sf[tid] = m; si[tid] = mi;
    __syncthreads();
    for (int s = 128; s > 0; s >>= 1) {
        if (tid < s) {
            if (sf[tid+s] > sf[tid] || (sf[tid+s] == sf[tid] && si[tid+s] < si[tid])) {
                sf[tid] = sf[tid+s]; si[tid] = si[tid+s];
            }
        }
        __syncthreads();
    }
    float M_ = sf[0];
    if (tid == 0) g_argmax[row] = si[0];
    __syncthreads();

    float sum = 0.f;
    for (int c = tid; c < VV; c += 256) sum += expf(x[c] - M_);
    sf[tid] = sum;
    __syncthreads();
    for (int s = 128; s > 0; s >>= 1) {
        if (tid < s) sf[tid] += sf[tid+s];
        __syncthreads();
    }
    float lse = M_ + logf(sf[0]);
    for (int c = tid; c < VV; c += 256) x[c] = x[c] - lse;
}

__global__ void k_tail_f(float* __restrict__ out)
{
    int r = blockIdx.x*blockDim.x + threadIdx.x;
    if (r < T1*BB) out[TBV + r] = (float)g_argmax[r];
}
__global__ void k_tail_i(int* __restrict__ out)
{
    int r = blockIdx.x*blockDim.x + threadIdx.x;
    if (r < T1*BB) out[r] = g_argmax[r];
}

// ---------------------------------------------------------------------------
extern "C" void kernel_launch(void* const* d_in, const int* in_sizes, int n_in,
                              void* d_out, int out_size)
{
    const int*   tgt   = (const int*)  d_in[0];
    const int*   lens  = (const int*)  d_in[1];
    const float* enc   = (const float*)d_in[2];
    const float* h0    = (const float*)d_in[3];
    const float* c0    = (const float*)d_in[4];
    const float* emb   = (const float*)d_in[5];
    const float* W_ih  = (const float*)d_in[6];
    const float* W_hh  = (const float*)d_in[7];
    const float* b_ih  = (const float*)d_in[8];
    const float* b_hh  = (const float*)d_in[9];
    const float* W_a   = (const float*)d_in[10];
    const float* W_c   = (const float*)d_in[11];
    const float* b_c   = (const float*)d_in[12];
    const float* W_o   = (const float*)d_in[13];
    const float* b_o   = (const float*)d_in[14];

    float *p_proj=nullptr, *p_xc=nullptr, *p_a2p=nullptr, *p_aha=nullptr,
          *p_lg=nullptr, *p_zero=nullptr;
    cudaGetSymbolAddress((void**)&p_proj, g_proj);
    cudaGetSymbolAddress((void**)&p_xc,   g_XC);
    cudaGetSymbolAddress((void**)&p_a2p,  g_A2part);
    cudaGetSymbolAddress((void**)&p_aha,  g_ah_all);
    cudaGetSymbolAddress((void**)&p_lg,   g_logits);
    cudaGetSymbolAddress((void**)&p_zero, g_zero);

    const bool big = (size_t)out_size >= TBV;
    float* logits = big ? (float*)d_out : p_lg;

    // init h, c
    k_init<<<64, 256>>>(h0, c0);

    // proj[(s,b),k] = enc[(s,b),:] @ W_a^T : M=2048, N=512, K=512
    sgemm<64,64,16,4,4,0><<<dim3(512/64, 2048/64, 1), 256>>>(
        enc, W_a, nullptr, p_proj, BB*SS, HH, HH, nullptr);

    // 31 sequential decoder steps
    for (int t = 0; t < T1; t++) {
        const float* ahp = (t == 0) ? p_zero : (p_aha + (size_t)(t-1)*BH);
        k_gates<<<dim3(4*HH/64, 1, 6), 256>>>(tgt, emb, W_ih, W_hh, ahp, t);
        k_lstm<<<64, 256>>>(b_ih, b_hh);
        k_attn<<<BB, HH>>>(lens, enc);
        // ah2_raw = [h2|ctx] @ W_c^T : M=32, N=512, K=1024, split-K=8
        sgemm<32,64,16,2,4,0><<<dim3(512/64, 1, 8), 256>>>(
            p_xc, W_c, nullptr, nullptr, BB, HH, 2*HH, p_a2p);
        k_ah2fin<<<64, 256>>>(b_c, t);
    }

    // logits = ah_all @ W_o^T + b_o : M=992, N=32000, K=512
    sgemm<64,64,16,4,4,0><<<dim3(VV/64, (T1*BB + 63)/64, 1), 256>>>(
        p_aha, W_o, b_o, logits, T1*BB, VV, HH, nullptr);

    // in-place log-softmax + argmax per row
    k_logsoftmax<<<T1*BB, 256>>>(logits);

    // output tail handling
    if (big && (size_t)out_size >= TBV + (size_t)T1*BB) {
        k_tail_f<<<4, 256>>>((float*)d_out);
    } else if (!big) {
        k_tail_i<<<4, 256>>>((int*)d_out);
    }
}